// round 1
// baseline (speedup 1.0000x reference)
#include <cuda_runtime.h>
#include <cuda_bf16.h>
#include <math.h>

// Problem constants (fixed shapes for this dataset)
#define QLEN   2048
#define HID    4096
#define NHEADS 32
#define ROWS   (NHEADS * QLEN)      // 65536 reduction rows
#define NCHUNK 512
#define RPC    (ROWS / NCHUNK)      // 128 rows per chunk
#define COLS_PER_BLOCK 1024         // 256 threads * float4

// ---- scratch (static device globals; no allocation allowed) ----
__device__ float  g_partial[NCHUNK][QLEN];   // 4 MB
__device__ double g_colsum[QLEN];
__device__ int    g_keep[QLEN];
__device__ int    g_nkeep;

// K1: partial column sums. grid = (QLEN/COLS_PER_BLOCK, NCHUNK), block = 256.
__global__ void k_partial(const float* __restrict__ w) {
    const int col   = blockIdx.x * COLS_PER_BLOCK + threadIdx.x * 4;
    const int chunk = blockIdx.y;
    const float4* p = reinterpret_cast<const float4*>(w);
    size_t idx = ((size_t)chunk * RPC * QLEN + col) >> 2;
    float4 acc = make_float4(0.f, 0.f, 0.f, 0.f);
#pragma unroll 8
    for (int i = 0; i < RPC; ++i) {
        float4 v = p[idx];
        acc.x += v.x; acc.y += v.y; acc.z += v.z; acc.w += v.w;
        idx += QLEN / 4;
    }
    *reinterpret_cast<float4*>(&g_partial[chunk][col]) = acc;
}

// K1b: deterministic finalize in double. grid = 8, block = 256 (2048 threads).
__global__ void k_finalize() {
    const int col = blockIdx.x * blockDim.x + threadIdx.x;
    double s = 0.0;
    for (int c = 0; c < NCHUNK; ++c) s += (double)g_partial[c][col];
    g_colsum[col] = s;
}

// K2: exact top-k selection + compaction. single block, 1024 threads.
__global__ void k_select(const int* __restrict__ startp, const int* __restrict__ lenp) {
    __shared__ double vals[QLEN];
    __shared__ int sa[QLEN], sb[QLEN];
    const int start = *startp;
    const int ilen  = *lenp;
    const int keep_k = (int)llrint((double)ilen * (1.0 - 0.3));  // matches Python round()
    const int t = threadIdx.x;

    for (int i = t; i < ilen; i += blockDim.x) vals[i] = g_colsum[start + i];
    __syncthreads();

    // flags per position, with jax.lax.top_k tie semantics (desc value, asc index)
    for (int p = t; p < QLEN; p += blockDim.x) {
        int f;
        if (p < start || p >= start + ilen) {
            f = 1;
        } else {
            const int i = p - start;
            const double v = vals[i];
            int cnt = 0;
            for (int j = 0; j < ilen; ++j) {
                const double u = vals[j];
                cnt += (u > v) || (u == v && j < i);
            }
            f = (cnt < keep_k) ? 1 : 0;
        }
        sa[p] = f;
    }
    __syncthreads();

    // inclusive scan (Hillis–Steele, ping-pong)
    int* src = sa; int* dst = sb;
    for (int off = 1; off < QLEN; off <<= 1) {
        for (int p = t; p < QLEN; p += blockDim.x)
            dst[p] = src[p] + ((p >= off) ? src[p - off] : 0);
        __syncthreads();
        int* tmp = src; src = dst; dst = tmp;
    }

    for (int p = t; p < QLEN; p += blockDim.x) {
        const int incl = src[p];
        const int prev = p ? src[p - 1] : 0;
        if (incl > prev) g_keep[incl - 1] = p;
    }
    if (t == 0) g_nkeep = src[QLEN - 1];
}

// K3: gather hs / pe rows. grid = (QLEN, 2), block = 256. y=0: hs, y=1: pe.
__global__ void k_gather_rows(const float* __restrict__ hs,
                              const float* __restrict__ pe,
                              float* __restrict__ out) {
    const int nk = g_nkeep;
    const int r  = blockIdx.x;
    if (r >= nk) return;
    const int srcrow = g_keep[r];
    const float* sp = (blockIdx.y ? pe : hs) + (size_t)srcrow * HID;
    float* dp = out + (size_t)blockIdx.y * nk * HID + (size_t)r * HID;
    const float4* s4 = reinterpret_cast<const float4*>(sp);
    float4* d4 = reinterpret_cast<float4*>(dp);
#pragma unroll 4
    for (int i = threadIdx.x; i < HID / 4; i += 256) d4[i] = s4[i];
}

// K4: gather attention_mask both dims. grid = (8, QLEN), block = 256.
__global__ void k_gather_mask(const float* __restrict__ mask,
                              float* __restrict__ out) {
    const int nk = g_nkeep;
    const int c = blockIdx.x * blockDim.x + threadIdx.x;
    const int r = blockIdx.y;
    if (r >= nk || c >= nk) return;
    const size_t base = 2ull * (size_t)nk * HID;
    out[base + (size_t)r * nk + c] =
        mask[(size_t)g_keep[r] * QLEN + g_keep[c]];
}

extern "C" void kernel_launch(void* const* d_in, const int* in_sizes, int n_in,
                              void* d_out, int out_size) {
    const float* hs   = (const float*)d_in[0];   // (1, 2048, 4096) f32
    const float* pe   = (const float*)d_in[1];   // (1, 2048, 4096) f32
    const float* mask = (const float*)d_in[2];   // (1, 1, 2048, 2048) f32
    const float* attn = (const float*)d_in[3];   // (1, 32, 2048, 2048) f32
    const int* startp = (const int*)d_in[4];     // scalar
    const int* lenp   = (const int*)d_in[5];     // scalar
    float* out = (float*)d_out;

    dim3 g1(QLEN / COLS_PER_BLOCK, NCHUNK);
    k_partial<<<g1, 256>>>(attn);
    k_finalize<<<QLEN / 256, 256>>>();
    k_select<<<1, 1024>>>(startp, lenp);
    dim3 g3(QLEN, 2);
    k_gather_rows<<<g3, 256>>>(hs, pe, out);
    dim3 g4(QLEN / 256, QLEN);
    k_gather_mask<<<g4, 256>>>(mask, out);
}

// round 2
// speedup vs baseline: 7.9134x; 7.9134x over previous
#include <cuda_runtime.h>
#include <cuda_bf16.h>
#include <math.h>

// Problem constants (fixed shapes for this dataset)
#define QLEN   2048
#define HID    4096
#define NHEADS 32
#define ROWS   (NHEADS * QLEN)      // 65536 reduction rows
#define NCHUNK 512
#define RPC    (ROWS / NCHUNK)      // 128 rows per chunk
#define COLS_PER_BLOCK 1024         // 256 threads * float4

// ---- scratch (static device globals; no allocation allowed) ----
__device__ float              g_partial[NCHUNK][QLEN];   // 4 MB
__device__ unsigned long long g_key[QLEN];               // monotone key of colsum
__device__ int                g_flag[QLEN];
__device__ int                g_keep[QLEN];
__device__ int                g_nkeep;

// Monotone map: double total order (finite) -> uint64 ascending order
__device__ __forceinline__ unsigned long long dkey(double d) {
    unsigned long long u = __double_as_longlong(d);
    return (u & 0x8000000000000000ull) ? ~u : (u | 0x8000000000000000ull);
}

// K1: partial column sums. grid = (QLEN/COLS_PER_BLOCK, NCHUNK), block = 256.
__global__ void k_partial(const float* __restrict__ w) {
    const int col   = blockIdx.x * COLS_PER_BLOCK + threadIdx.x * 4;
    const int chunk = blockIdx.y;
    const float4* p = reinterpret_cast<const float4*>(w);
    size_t idx = ((size_t)chunk * RPC * QLEN + col) >> 2;
    float4 acc = make_float4(0.f, 0.f, 0.f, 0.f);
#pragma unroll 8
    for (int i = 0; i < RPC; ++i) {
        float4 v = p[idx];
        acc.x += v.x; acc.y += v.y; acc.z += v.z; acc.w += v.w;
        idx += QLEN / 4;
    }
    *reinterpret_cast<float4*>(&g_partial[chunk][col]) = acc;
}

// K1b: deterministic finalize in double, emit integer key. grid = 8, block = 256.
__global__ void k_finalize() {
    const int col = blockIdx.x * blockDim.x + threadIdx.x;
    double s = 0.0;
    for (int c = 0; c < NCHUNK; ++c) s += (double)g_partial[c][col];
    g_key[col] = dkey(s);
}

// K2a: parallel rank counting -> keep flag per position.
// grid = QLEN blocks, block = 256. All compares are 64-bit integer.
__global__ void k_rank(const int* __restrict__ startp, const int* __restrict__ lenp) {
    const int start = *startp;
    const int ilen  = *lenp;
    const int p = blockIdx.x;
    const int t = threadIdx.x;
    __shared__ int s_cnt;

    if (p < start || p >= start + ilen) {
        if (t == 0) g_flag[p] = 1;
        return;
    }
    const int keep_k = (int)llrint((double)ilen * (1.0 - 0.3));
    const int i = p - start;
    const unsigned long long v = g_key[p];
    if (t == 0) s_cnt = 0;
    __syncthreads();
    int c = 0;
    for (int j = t; j < ilen; j += 256) {
        const unsigned long long u = g_key[start + j];
        c += (u > v) || (u == v && j < i);
    }
    // warp reduce then shared atomic
    for (int off = 16; off; off >>= 1) c += __shfl_down_sync(0xffffffffu, c, off);
    if ((t & 31) == 0) atomicAdd(&s_cnt, c);
    __syncthreads();
    if (t == 0) g_flag[p] = (s_cnt < keep_k) ? 1 : 0;
}

// K2b: compact flags into sorted keep list. single block, 1024 threads, int-only.
__global__ void k_compact() {
    __shared__ int sa[QLEN], sb[QLEN];
    const int t = threadIdx.x;
    for (int p = t; p < QLEN; p += blockDim.x) sa[p] = g_flag[p];
    __syncthreads();
    int* src = sa; int* dst = sb;
    for (int off = 1; off < QLEN; off <<= 1) {
        for (int p = t; p < QLEN; p += blockDim.x)
            dst[p] = src[p] + ((p >= off) ? src[p - off] : 0);
        __syncthreads();
        int* tmp = src; src = dst; dst = tmp;
    }
    for (int p = t; p < QLEN; p += blockDim.x) {
        const int incl = src[p];
        const int prev = p ? src[p - 1] : 0;
        if (incl > prev) g_keep[incl - 1] = p;
    }
    if (t == 0) g_nkeep = src[QLEN - 1];
}

// K3: gather hs / pe rows. grid = (QLEN, 2), block = 256. y=0: hs, y=1: pe.
__global__ void k_gather_rows(const float* __restrict__ hs,
                              const float* __restrict__ pe,
                              float* __restrict__ out) {
    const int nk = g_nkeep;
    const int r  = blockIdx.x;
    if (r >= nk) return;
    const int srcrow = g_keep[r];
    const float* sp = (blockIdx.y ? pe : hs) + (size_t)srcrow * HID;
    float* dp = out + (size_t)blockIdx.y * nk * HID + (size_t)r * HID;
    const float4* s4 = reinterpret_cast<const float4*>(sp);
    float4* d4 = reinterpret_cast<float4*>(dp);
#pragma unroll 4
    for (int i = threadIdx.x; i < HID / 4; i += 256) d4[i] = s4[i];
}

// K4: gather attention_mask both dims. grid = (8, QLEN), block = 256.
__global__ void k_gather_mask(const float* __restrict__ mask,
                              float* __restrict__ out) {
    const int nk = g_nkeep;
    const int c = blockIdx.x * blockDim.x + threadIdx.x;
    const int r = blockIdx.y;
    if (r >= nk || c >= nk) return;
    const size_t base = 2ull * (size_t)nk * HID;
    out[base + (size_t)r * nk + c] =
        mask[(size_t)g_keep[r] * QLEN + g_keep[c]];
}

extern "C" void kernel_launch(void* const* d_in, const int* in_sizes, int n_in,
                              void* d_out, int out_size) {
    const float* hs   = (const float*)d_in[0];   // (1, 2048, 4096) f32
    const float* pe   = (const float*)d_in[1];   // (1, 2048, 4096) f32
    const float* mask = (const float*)d_in[2];   // (1, 1, 2048, 2048) f32
    const float* attn = (const float*)d_in[3];   // (1, 32, 2048, 2048) f32
    const int* startp = (const int*)d_in[4];     // scalar
    const int* lenp   = (const int*)d_in[5];     // scalar
    float* out = (float*)d_out;

    dim3 g1(QLEN / COLS_PER_BLOCK, NCHUNK);
    k_partial<<<g1, 256>>>(attn);
    k_finalize<<<QLEN / 256, 256>>>();
    k_rank<<<QLEN, 256>>>(startp, lenp);
    k_compact<<<1, 1024>>>();
    dim3 g3(QLEN, 2);
    k_gather_rows<<<g3, 256>>>(hs, pe, out);
    dim3 g4(QLEN / 256, QLEN);
    k_gather_mask<<<g4, 256>>>(mask, out);
}

// round 4
// speedup vs baseline: 10.6213x; 1.3422x over previous
#include <cuda_runtime.h>
#include <cuda_bf16.h>
#include <math.h>

#define QLEN   2048
#define HID    4096
#define NHEADS 32
#define ROWS   (NHEADS * QLEN)      // 65536
#define NCHUNK 512
#define RPC    (ROWS / NCHUNK)      // 128 rows per chunk
#define COLS_PER_BLOCK 1024         // 256 threads * float4

// ---- scratch ----
__device__ float              g_partial[NCHUNK][QLEN];   // 4 MB
__device__ unsigned long long g_key[QLEN];
__device__ int                g_flag[QLEN];
__device__ int                g_keep[QLEN];
__device__ int                g_nkeep;

__device__ __forceinline__ unsigned long long dkey(double d) {
    unsigned long long u = __double_as_longlong(d);
    return (u & 0x8000000000000000ull) ? ~u : (u | 0x8000000000000000ull);
}

// K1: partial column sums. grid=(2, NCHUNK), block=256.
// Front-batched 16-deep LDG.128 (streaming), dual accumulators.
__global__ void k_partial(const float* __restrict__ w) {
    const int col   = blockIdx.x * COLS_PER_BLOCK + threadIdx.x * 4;
    const int chunk = blockIdx.y;
    const float4* p = reinterpret_cast<const float4*>(w)
                    + (((size_t)chunk * RPC * QLEN + col) >> 2);
    float4 a0 = make_float4(0.f,0.f,0.f,0.f);
    float4 a1 = make_float4(0.f,0.f,0.f,0.f);
#pragma unroll
    for (int i = 0; i < RPC; i += 16) {
        float4 v[16];
#pragma unroll
        for (int j = 0; j < 16; ++j)
            v[j] = __ldcs(p + (size_t)(i + j) * (QLEN / 4));
#pragma unroll
        for (int j = 0; j < 16; j += 2) {
            a0.x += v[j].x;   a0.y += v[j].y;   a0.z += v[j].z;   a0.w += v[j].w;
            a1.x += v[j+1].x; a1.y += v[j+1].y; a1.z += v[j+1].z; a1.w += v[j+1].w;
        }
    }
    float4 r;
    r.x = a0.x + a1.x; r.y = a0.y + a1.y; r.z = a0.z + a1.z; r.w = a0.w + a1.w;
    *reinterpret_cast<float4*>(&g_partial[chunk][col]) = r;
}

// K1b: finalize in double with 8 independent accumulators. grid=8, block=256.
__global__ void k_finalize() {
    const int col = blockIdx.x * blockDim.x + threadIdx.x;
    double a[8] = {0,0,0,0,0,0,0,0};
#pragma unroll 8
    for (int c = 0; c < NCHUNK; c += 8) {
#pragma unroll
        for (int q = 0; q < 8; ++q) a[q] += (double)g_partial[c + q][col];
    }
    double s = ((a[0]+a[1]) + (a[2]+a[3])) + ((a[4]+a[5]) + (a[6]+a[7]));
    g_key[col] = dkey(s);
}

// K2a: rank counting with keys staged in smem. grid=QLEN/8, block=256 (8 warps,
// one position per warp).
__global__ void k_rank(const int* __restrict__ startp, const int* __restrict__ lenp) {
    __shared__ unsigned long long sk[QLEN];
    const int start = *startp;
    const int ilen  = *lenp;
    const int t = threadIdx.x;
    for (int i = t; i < ilen; i += 256) sk[i] = g_key[start + i];
    __syncthreads();
    const int w = t >> 5, lane = t & 31;
    const int p = blockIdx.x * 8 + w;
    if (p >= QLEN) return;
    if (p < start || p >= start + ilen) {
        if (lane == 0) g_flag[p] = 1;
        return;
    }
    const int keep_k = (int)llrint((double)ilen * (1.0 - 0.3));
    const int i = p - start;
    const unsigned long long v = sk[i];
    int c = 0;
    for (int j = lane; j < ilen; j += 32) {
        const unsigned long long u = sk[j];
        c += (u > v) || (u == v && j < i);
    }
#pragma unroll
    for (int off = 16; off; off >>= 1) c += __shfl_down_sync(0xffffffffu, c, off);
    if (lane == 0) g_flag[p] = (c < keep_k) ? 1 : 0;
}

// K2b: compact via shuffle scan. single block, 1024 threads, 2 elems/thread.
__global__ void k_compact() {
    const int t = threadIdx.x;
    const int lane = t & 31, w = t >> 5;
    const int f0 = g_flag[2 * t];
    const int f1 = g_flag[2 * t + 1];
    const int sum = f0 + f1;
    int v = sum;
#pragma unroll
    for (int o = 1; o < 32; o <<= 1) {
        int n = __shfl_up_sync(0xffffffffu, v, o);
        if (lane >= o) v += n;
    }
    __shared__ int wsum[32];
    if (lane == 31) wsum[w] = v;
    __syncthreads();
    if (w == 0) {
        int x = wsum[lane];
#pragma unroll
        for (int o = 1; o < 32; o <<= 1) {
            int n = __shfl_up_sync(0xffffffffu, x, o);
            if (lane >= o) x += n;
        }
        wsum[lane] = x;
    }
    __syncthreads();
    const int base = (w ? wsum[w - 1] : 0) + v - sum;   // exclusive prefix @ 2t
    if (f0) g_keep[base] = 2 * t;
    if (f1) g_keep[base + f0] = 2 * t + 1;
    if (t == 1023) g_nkeep = wsum[31];
}

// K3: gather hs / pe rows. grid=(QLEN, 2), block=256.
__global__ void k_gather_rows(const float* __restrict__ hs,
                              const float* __restrict__ pe,
                              float* __restrict__ out) {
    const int nk = g_nkeep;
    const int r  = blockIdx.x;
    if (r >= nk) return;
    const int srcrow = g_keep[r];
    const float* sp = (blockIdx.y ? pe : hs) + (size_t)srcrow * HID;
    float* dp = out + (size_t)blockIdx.y * nk * HID + (size_t)r * HID;
    const float4* s4 = reinterpret_cast<const float4*>(sp);
    float4* d4 = reinterpret_cast<float4*>(dp);
#pragma unroll 4
    for (int i = threadIdx.x; i < HID / 4; i += 256) d4[i] = s4[i];
}

// K4: gather attention_mask both dims. grid=(8, QLEN), block=256.
__global__ void k_gather_mask(const float* __restrict__ mask,
                              float* __restrict__ out) {
    const int nk = g_nkeep;
    const int c = blockIdx.x * blockDim.x + threadIdx.x;
    const int r = blockIdx.y;
    if (r >= nk || c >= nk) return;
    const size_t base = 2ull * (size_t)nk * HID;
    out[base + (size_t)r * nk + c] =
        mask[(size_t)g_keep[r] * QLEN + g_keep[c]];
}

extern "C" void kernel_launch(void* const* d_in, const int* in_sizes, int n_in,
                              void* d_out, int out_size) {
    const float* hs   = (const float*)d_in[0];
    const float* pe   = (const float*)d_in[1];
    const float* mask = (const float*)d_in[2];
    const float* attn = (const float*)d_in[3];
    const int* startp = (const int*)d_in[4];
    const int* lenp   = (const int*)d_in[5];
    float* out = (float*)d_out;

    dim3 g1(QLEN / COLS_PER_BLOCK, NCHUNK);
    k_partial<<<g1, 256>>>(attn);
    k_finalize<<<QLEN / 256, 256>>>();
    k_rank<<<QLEN / 8, 256>>>(startp, lenp);
    k_compact<<<1, 1024>>>();
    dim3 g3(QLEN, 2);
    k_gather_rows<<<g3, 256>>>(hs, pe, out);
    dim3 g4(QLEN / 256, QLEN);
    k_gather_mask<<<g4, 256>>>(mask, out);
}